// round 12
// baseline (speedup 1.0000x reference)
#include <cuda_runtime.h>
#include <cstdint>

// ---------------- Problem constants ----------------
#define E_TOTAL   500000
#define TILE_M    128
#define NTILES    ((E_TOTAL + TILE_M - 1) / TILE_M)   // 3907
#define NTHREADS  512

// SMEM: ring of 5 A-chunk slots [128 rows x 64 k] tf32 = 32KB each -> 160KB
#define SM_MBAR    (5 * 32768)             // 163840
#define SMEM_TOTAL (SM_MBAR + 128)         // 163968 (1 CTA/SM)

#define FULL_BAR(sb, s)  ((sb) + SM_MBAR + (uint32_t)(s) * 8u)
#define EMPTY_BAR(sb, s) ((sb) + SM_MBAR + 40u + (uint32_t)(s) * 8u)

// Repacked W in fragment order: idx = c*1024 + wn*512 + (nf*4+t)*32 + lane.
__device__ uint4 Wrep[5120];   // 80KB, tf32-converted

// ---------------- helpers ----------------
__device__ __forceinline__ uint32_t smem_u32(const void* p) {
    uint32_t a;
    asm("{ .reg .u64 t; cvta.to.shared.u64 t, %1; cvt.u32.u64 %0, t; }"
        : "=r"(a) : "l"(p));
    return a;
}

__device__ __forceinline__ uint32_t f2tf32(float f) {
    uint32_t r;
    asm("cvt.rna.tf32.f32 %0, %1;" : "=r"(r) : "f"(f));
    return r;
}

// A-tile layout: [rows x 64 cols] tf32, 256B/row, cols k-permuted per 16-col
// group: quad (grp,t) holds cols {16grp+t, +4, +8, +12}.
// Swizzle: XOR byte bits[6:4] with sw(row)=((row&1)<<2)|(row&2)|((row>>2)&1).
__device__ __forceinline__ uint32_t tileoff(int row, int grp, int t) {
    uint32_t o  = (uint32_t)(row * 256 + grp * 64 + t * 16);
    uint32_t sw = (((uint32_t)row & 1u) << 2) | ((uint32_t)row & 2u) |
                  (((uint32_t)row >> 2) & 1u);
    return o ^ (sw << 4);
}

__device__ __forceinline__ void sts128(uint32_t addr, uint32_t a, uint32_t b,
                                       uint32_t c, uint32_t d) {
    asm volatile("st.shared.v4.b32 [%0], {%1,%2,%3,%4};"
                 :: "r"(addr), "r"(a), "r"(b), "r"(c), "r"(d) : "memory");
}

__device__ __forceinline__ void lds128(uint32_t addr, uint32_t* r) {
    asm volatile("ld.shared.v4.b32 {%0,%1,%2,%3}, [%4];"
                 : "=r"(r[0]), "=r"(r[1]), "=r"(r[2]), "=r"(r[3])
                 : "r"(addr));
}

__device__ __forceinline__ void mma_tf32(float* c, uint32_t a0, uint32_t a1,
                                         uint32_t a2, uint32_t a3,
                                         uint32_t b0, uint32_t b1) {
    asm volatile(
        "mma.sync.aligned.m16n8k8.row.col.f32.tf32.tf32.f32 "
        "{%0,%1,%2,%3},{%4,%5,%6,%7},{%8,%9},{%0,%1,%2,%3};"
        : "+f"(c[0]), "+f"(c[1]), "+f"(c[2]), "+f"(c[3])
        : "r"(a0), "r"(a1), "r"(a2), "r"(a3), "r"(b0), "r"(b1));
}

// 4x4 transpose across 4 consecutive lanes (sub = lane&3), in-place.
__device__ __forceinline__ void transpose4(float4& v, int sub) {
    float t0 = (sub & 1) ? v.x : v.y;
    float t1 = (sub & 1) ? v.z : v.w;
    t0 = __shfl_xor_sync(0xffffffffu, t0, 1);
    t1 = __shfl_xor_sync(0xffffffffu, t1, 1);
    if (sub & 1) { v.x = t0; v.z = t1; } else { v.y = t0; v.w = t1; }
    float t2 = (sub & 2) ? v.x : v.z;
    float t3 = (sub & 2) ? v.y : v.w;
    t2 = __shfl_xor_sync(0xffffffffu, t2, 2);
    t3 = __shfl_xor_sync(0xffffffffu, t3, 2);
    if (sub & 2) { v.x = t2; v.y = t3; } else { v.z = t2; v.w = t3; }
}

// ---------------- mbarrier ----------------
#define MBARRIER_INIT(mbar, cnt) \
    asm volatile("mbarrier.init.shared.b64 [%0], %1;" \
                 :: "r"((uint32_t)(mbar)), "r"((uint32_t)(cnt)) : "memory")

#define MBARRIER_ARRIVE_REL(mbar) \
    asm volatile("mbarrier.arrive.release.cta.shared::cta.b64 _, [%0];" \
                 :: "r"((uint32_t)(mbar)) : "memory")

#define MBARRIER_WAIT_PARITY(mbar, parity) do {                                    \
    uint32_t _m = (uint32_t)(mbar);                                                \
    uint32_t _p = (uint32_t)(parity);                                              \
    asm volatile(                                                                  \
        "{\n\t.reg .pred P1;\n\t"                                                  \
        "WAIT_LOOP_%=:\n\t"                                                        \
        "mbarrier.try_wait.parity.acquire.cta.shared::cta.b64 P1, [%0], %1, 0x989680;\n\t" \
        "@P1 bra.uni WAIT_DONE_%=;\n\t"                                            \
        "bra.uni WAIT_LOOP_%=;\n\t"                                                \
        "WAIT_DONE_%=:\n\t}"                                                       \
        :: "r"(_m), "r"(_p) : "memory");                                           \
} while (0)

// ---------------- W repack kernel (runs once, tiny) ----------------
__global__ void repack_w_kernel(const float* __restrict__ W) {
    int idx = blockIdx.x * blockDim.x + threadIdx.x;
    if (idx >= 5120) return;
    int tig = idx & 3;
    int t   = (idx >> 5) & 3;
    int nf  = (idx >> 7) & 3;
    int wn  = (idx >> 9) & 1;
    int c   = idx >> 10;
    int g   = (idx >> 2) & 7;
    int n   = wn * 32 + nf * 8 + g;
    int col = c * 64 + t * 16 + tig;
    const float* wr = W + (size_t)n * 320 + col;
    uint4 v;
    v.x = f2tf32(wr[0]);
    v.y = f2tf32(wr[4]);
    v.z = f2tf32(wr[8]);
    v.w = f2tf32(wr[12]);
    Wrep[idx] = v;
}

// ---------------- producer pieces ----------------
// Edge mapping within a warp's 16 edges: elem i (0..7) + half -> edge offset
// off(i) = 8*(i>>2) + 2*(i&3) + half.  Same mapping for gather and STS.
__device__ __forceinline__ void xpose_sts16(uint32_t buf, int we0, int half,
                                            int grp, int sub, const float4* S) {
#pragma unroll
    for (int i = 0; i < 8; i++) {
        float4 v = S[i];
        transpose4(v, sub);
        int row = we0 + 8 * (i >> 2) + 2 * (i & 3) + half;
        sts128(buf + tileoff(row, grp, sub),
               f2tf32(v.x), f2tf32(v.y), f2tf32(v.z), f2tf32(v.w));
    }
}

__device__ __forceinline__ void gather_x16(const float* __restrict__ x, int base,
                                           int q, int half, float4* S) {
#pragma unroll
    for (int i = 0; i < 8; i++) {
        int e = base + 8 * (i >> 2) + 2 * (i & 3) + half;
        if (e > E_TOTAL - 1) e = E_TOTAL - 1;
        S[i] = __ldg((const float4*)x + (size_t)e * 16 + q);
    }
}

// Gather a full neighbor pair (16 edges) and produce min/max streams.
__device__ __forceinline__ void gather_pair16(const float* __restrict__ x,
                                              int cA, int cB, int q, int half,
                                              float4* MN, float4* MX) {
#pragma unroll
    for (int i = 0; i < 8; i++) {
        int l  = 8 * (i >> 2) + 2 * (i & 3) + half;
        int ia = __shfl_sync(0xffffffffu, cA, l);
        int ib = __shfl_sync(0xffffffffu, cB, l);
        float4 va = make_float4(0.f, 0.f, 0.f, 0.f);
        float4 vb = make_float4(0.f, 0.f, 0.f, 0.f);
        if (ia >= 0) va = __ldg((const float4*)x + (size_t)ia * 16 + q);
        if (ib >= 0) vb = __ldg((const float4*)x + (size_t)ib * 16 + q);
        MN[i] = make_float4(fminf(va.x, vb.x), fminf(va.y, vb.y),
                            fminf(va.z, vb.z), fminf(va.w, vb.w));
        MX[i] = make_float4(fmaxf(va.x, vb.x), fmaxf(va.y, vb.y),
                            fmaxf(va.z, vb.z), fmaxf(va.w, vb.w));
    }
}

// ---------------- kernel ----------------
// K=320 chunks: c0:x c1:min01 c2:max01 c3:min23 c4:max23
// 512 threads, 1 CTA/SM. Warps 0-7: consumers (m32 x n32, 4m x 2n).
// Warps 8-15: producers (16 edges each). 5-slot ring, slot == chunk index.
// Parity convention (validated on HW in R5): fresh barrier passes wait(1);
// wait(0) blocks until first completion. Producers start empty-phase=1,
// consumers start full-phase=0; both flip on ring wrap (= tile boundary).
__global__ void __launch_bounds__(NTHREADS, 1)
meshconv_kernel(const float* __restrict__ x, const int* __restrict__ nbr,
                const float* __restrict__ bias, float* __restrict__ out) {
    extern __shared__ char smem[];
    const uint32_t sb = smem_u32(smem);
    const int tid = threadIdx.x;
    const int lid = tid & 31, wid = tid >> 5;

    if (tid == 0) {
#pragma unroll
        for (int s = 0; s < 5; s++) {
            MBARRIER_INIT(FULL_BAR(sb, s), 8);    // 8 producer warps
            MBARRIER_INIT(EMPTY_BAR(sb, s), 8);   // 8 consumer warps
        }
    }
    __syncthreads();

    if (wid < 8) {
        // ====================== CONSUMERS ======================
        const int wm = wid & 3, wn = wid >> 2;
        const int g = lid >> 2, tig = lid & 3;
        const uint4* wrbase = Wrep + wn * 512 + lid;

        float bv[4][2];
#pragma unroll
        for (int nf = 0; nf < 4; nf++) {
            int bc = wn * 32 + nf * 8 + tig * 2;
            bv[nf][0] = __ldg(bias + bc);
            bv[nf][1] = __ldg(bias + bc + 1);
        }

        int ph = 0;
        for (int tile = blockIdx.x; tile < NTILES; tile += gridDim.x) {
            const int tbase = tile * TILE_M;
            float acc[2][4][4];
#pragma unroll
            for (int ms = 0; ms < 2; ms++)
#pragma unroll
                for (int nf = 0; nf < 4; nf++) {
                    acc[ms][nf][0] = bv[nf][0];
                    acc[ms][nf][1] = bv[nf][1];
                    acc[ms][nf][2] = bv[nf][0];
                    acc[ms][nf][3] = bv[nf][1];
                }

#pragma unroll
            for (int c = 0; c < 5; c++) {
                const uint4* wrc = wrbase + c * 1024;
                // Prefetch B for t=0,1 BEFORE the wait (static data).
                uint4 Bpre[2][4];
#pragma unroll
                for (int tt = 0; tt < 2; tt++)
#pragma unroll
                    for (int nf = 0; nf < 4; nf++)
                        Bpre[tt][nf] = __ldg(wrc + (nf * 4 + tt) * 32);

                MBARRIER_WAIT_PARITY(FULL_BAR(sb, c), ph);
                const uint32_t aB = sb + (uint32_t)c * 32768u;
#pragma unroll
                for (int t = 0; t < 4; t++) {
                    uint4 Bq[4];
#pragma unroll
                    for (int nf = 0; nf < 4; nf++)
                        Bq[nf] = (t < 2) ? Bpre[t][nf]
                                         : __ldg(wrc + (nf * 4 + t) * 32);
                    uint32_t Af[2][2][4];
#pragma unroll
                    for (int ms = 0; ms < 2; ms++)
#pragma unroll
                        for (int rh = 0; rh < 2; rh++)
                            lds128(aB + tileoff(wm * 32 + ms * 16 + rh * 8 + g,
                                                t, tig),
                                   Af[ms][rh]);
#pragma unroll
                    for (int ms = 0; ms < 2; ms++)
#pragma unroll
                        for (int nf = 0; nf < 4; nf++) {
                            mma_tf32(acc[ms][nf],
                                     Af[ms][0][0], Af[ms][1][0],
                                     Af[ms][0][1], Af[ms][1][1],
                                     Bq[nf].x, Bq[nf].y);
                            mma_tf32(acc[ms][nf],
                                     Af[ms][0][2], Af[ms][1][2],
                                     Af[ms][0][3], Af[ms][1][3],
                                     Bq[nf].z, Bq[nf].w);
                        }
                }
                __syncwarp();
                if (lid == 0) MBARRIER_ARRIVE_REL(EMPTY_BAR(sb, c));
            }
            ph ^= 1;

            // epilogue: pure stores
#pragma unroll
            for (int ms = 0; ms < 2; ms++) {
#pragma unroll
                for (int nf = 0; nf < 4; nf++) {
                    const int e0  = tbase + wm * 32 + ms * 16 + g;
                    const int e1  = e0 + 8;
                    const int col = wn * 32 + nf * 8 + tig * 2;
                    if (e0 < E_TOTAL)
                        *(float2*)(out + (size_t)e0 * 64 + col) =
                            make_float2(acc[ms][nf][0], acc[ms][nf][1]);
                    if (e1 < E_TOTAL)
                        *(float2*)(out + (size_t)e1 * 64 + col) =
                            make_float2(acc[ms][nf][2], acc[ms][nf][3]);
                }
            }
        }
    } else {
        // ====================== PRODUCERS ======================
        const int pw = wid - 8;
        const int we0 = pw * 16;
        const int q = lid & 15, half = lid >> 4, sub = lid & 3, grp = q >> 2;

        int tile = blockIdx.x;
        int NBx = -1, NBy = -1, NBz = -1, NBw = -1;
        {
            int e = tile * TILE_M + we0 + (lid & 15);
            if (e > E_TOTAL - 1) e = E_TOTAL - 1;
            if (lid < 16) {
                int4 v = __ldg((const int4*)nbr + e);
                NBx = v.x; NBy = v.y; NBz = v.z; NBw = v.w;
            }
        }

        int ph = 1;   // fresh empty barriers pass wait(1)
        for (; tile < NTILES; tile += gridDim.x) {
            const int base = tile * TILE_M + we0;

            // c0: x rows (gather BEFORE the wait)
            {
                float4 S[8];
                gather_x16(x, base, q, half, S);
                MBARRIER_WAIT_PARITY(EMPTY_BAR(sb, 0), ph);
                xpose_sts16(sb + 0 * 32768u, we0, half, grp, sub, S);
                __syncwarp();
                if (lid == 0) MBARRIER_ARRIVE_REL(FULL_BAR(sb, 0));
            }

            // pair0 -> c1 (min01), c2 (max01)
            {
                float4 MN[8], MX[8];
                gather_pair16(x, NBx, NBy, q, half, MN, MX);
                MBARRIER_WAIT_PARITY(EMPTY_BAR(sb, 1), ph);
                xpose_sts16(sb + 1 * 32768u, we0, half, grp, sub, MN);
                __syncwarp();
                if (lid == 0) MBARRIER_ARRIVE_REL(FULL_BAR(sb, 1));
                MBARRIER_WAIT_PARITY(EMPTY_BAR(sb, 2), ph);
                xpose_sts16(sb + 2 * 32768u, we0, half, grp, sub, MX);
                __syncwarp();
                if (lid == 0) MBARRIER_ARRIVE_REL(FULL_BAR(sb, 2));
            }

            // pair1 -> c3 (min23), c4 (max23); prefetch next tile's NB
            {
                float4 MN[8], MX[8];
                gather_pair16(x, NBz, NBw, q, half, MN, MX);
                int tn = tile + gridDim.x;
                if (tn >= NTILES) tn = tile;
                {
                    int e = tn * TILE_M + we0 + (lid & 15);
                    if (e > E_TOTAL - 1) e = E_TOTAL - 1;
                    if (lid < 16) {
                        int4 v = __ldg((const int4*)nbr + e);
                        NBx = v.x; NBy = v.y; NBz = v.z; NBw = v.w;
                    }
                }
                MBARRIER_WAIT_PARITY(EMPTY_BAR(sb, 3), ph);
                xpose_sts16(sb + 3 * 32768u, we0, half, grp, sub, MN);
                __syncwarp();
                if (lid == 0) MBARRIER_ARRIVE_REL(FULL_BAR(sb, 3));
                MBARRIER_WAIT_PARITY(EMPTY_BAR(sb, 4), ph);
                xpose_sts16(sb + 4 * 32768u, we0, half, grp, sub, MX);
                __syncwarp();
                if (lid == 0) MBARRIER_ARRIVE_REL(FULL_BAR(sb, 4));
            }
            ph ^= 1;
        }
    }
}

// ---------------- launch ----------------
extern "C" void kernel_launch(void* const* d_in, const int* in_sizes, int n_in,
                              void* d_out, int out_size) {
    const float* x   = (const float*)d_in[0];
    const int*   nbr = (const int*)d_in[1];
    const float* W   = (const float*)d_in[2];
    const float* b   = (const float*)d_in[3];
    float* out = (float*)d_out;

    int nsm = 0;
    cudaDeviceGetAttribute(&nsm, cudaDevAttrMultiProcessorCount, 0);
    if (nsm <= 0) nsm = 148;

    repack_w_kernel<<<20, 256>>>(W);

    cudaFuncSetAttribute(meshconv_kernel,
                         cudaFuncAttributeMaxDynamicSharedMemorySize, SMEM_TOTAL);
    meshconv_kernel<<<nsm, NTHREADS, SMEM_TOTAL>>>(x, nbr, b, out);
}

// round 14
// speedup vs baseline: 2.7535x; 2.7535x over previous
#include <cuda_runtime.h>
#include <cuda_fp16.h>
#include <cstdint>

// ---------------- Problem constants ----------------
#define E_TOTAL   500000
#define TILE_M    128
#define NTILES    ((E_TOTAL + TILE_M - 1) / TILE_M)   // 3907
#define NTHREADS  256

// SMEM: 3 A-chunk buffers [128 rows x 64 halfs] = 16KB each -> 48KB, 2 CTAs/SM
#define SMEM_TOTAL (3 * 16384)

// Repacked fp16 W in B-fragment order:
// idx = (((c*2 + wn)*4 + nf)*2 + tp)*32 + lane; uint4 = b-regs for steps 2tp,2tp+1.
__device__ uint4 WrepH[2560];   // 40KB

// ---------------- helpers ----------------
__device__ __forceinline__ uint32_t smem_u32(const void* p) {
    uint32_t a;
    asm("{ .reg .u64 t; cvta.to.shared.u64 t, %1; cvt.u32.u64 %0, t; }"
        : "=r"(a) : "l"(p));
    return a;
}

__device__ __forceinline__ uint32_t f2h2(float a, float b) {
    __half2 h = __floats2half2_rn(a, b);
    return *reinterpret_cast<uint32_t*>(&h);
}

// A-chunk layout: row-major fp16, 128B per row (64 halfs), 16B-group swizzle:
// group position p (0..7) stored at p ^ (row & 7).
// Producer 8B-slot address (slot q = cols 4q..4q+3):
__device__ __forceinline__ uint32_t arow_off(int row, int q) {
    return (uint32_t)(row * 128 + (((q >> 1) ^ (row & 7)) << 4) + ((q & 1) << 3));
}

__device__ __forceinline__ void sts64(uint32_t addr, uint32_t a, uint32_t b) {
    asm volatile("st.shared.v2.b32 [%0], {%1,%2};"
                 :: "r"(addr), "r"(a), "r"(b) : "memory");
}

// ldmatrix x4 (b16): canonical A m16k16 fragment load.
__device__ __forceinline__ void ldsm_x4(uint32_t* r, uint32_t addr) {
    asm volatile("ldmatrix.sync.aligned.m8n8.x4.shared.b16 {%0,%1,%2,%3}, [%4];"
                 : "=r"(r[0]), "=r"(r[1]), "=r"(r[2]), "=r"(r[3])
                 : "r"(addr));
}

// m16n8k16 fp16 mma, fp32 accum: D = A*B + D
__device__ __forceinline__ void mma_f16(float* c, const uint32_t* a, uint32_t b0,
                                        uint32_t b1) {
    asm volatile(
        "mma.sync.aligned.m16n8k16.row.col.f32.f16.f16.f32 "
        "{%0,%1,%2,%3},{%4,%5,%6,%7},{%8,%9},{%0,%1,%2,%3};"
        : "+f"(c[0]), "+f"(c[1]), "+f"(c[2]), "+f"(c[3])
        : "r"(a[0]), "r"(a[1]), "r"(a[2]), "r"(a[3]), "r"(b0), "r"(b1));
}

// ---------------- W repack kernel (runs once, tiny) ----------------
__global__ void repack_w_h(const float* __restrict__ W) {
    int idx = blockIdx.x * blockDim.x + threadIdx.x;
    if (idx >= 2560) return;
    int lane = idx & 31;
    int tp   = (idx >> 5) & 1;
    int nf   = (idx >> 6) & 3;
    int wn   = (idx >> 8) & 1;
    int c    = idx >> 9;
    int g    = lane >> 2, tig = lane & 3;
    int n    = wn * 32 + nf * 8 + g;
    const float* wr = W + (size_t)n * 320;
    int kA = c * 64 + (2 * tp) * 16 + 2 * tig;
    int kB = kA + 16;
    uint4 v;
    v.x = f2h2(wr[kA], wr[kA + 1]);
    v.y = f2h2(wr[kA + 8], wr[kA + 9]);
    v.z = f2h2(wr[kB], wr[kB + 1]);
    v.w = f2h2(wr[kB + 8], wr[kB + 9]);
    WrepH[idx] = v;
}

// ---------------- producer pieces ----------------
// Warp owns 16 edges. Lane: q = lid&15 (8B col-slot), half = lid>>4.
// Iter i covers edges 2i (half0) and 2i+1 (half1).
__device__ __forceinline__ void stage_x(const float* __restrict__ x, int basew,
                                        uint32_t buf, int we0, int q, int half) {
#pragma unroll
    for (int i = 0; i < 8; i++) {
        int l = 2 * i + half;
        int e = basew + l;
        if (e > E_TOTAL - 1) e = E_TOTAL - 1;
        float4 v = __ldg((const float4*)x + (size_t)e * 16 + q);
        sts64(buf + arow_off(we0 + l, q), f2h2(v.x, v.y), f2h2(v.z, v.w));
    }
}

// Gather neighbor pair, STS min stream, hold max stream (fp32).
__device__ __forceinline__ void pair_do(const float* __restrict__ x, int cA,
                                        int cB, int q, int half, int we0,
                                        uint32_t bufMin, float4* MX) {
#pragma unroll
    for (int i = 0; i < 8; i++) {
        int l  = 2 * i + half;
        int ia = __shfl_sync(0xffffffffu, cA, l);
        int ib = __shfl_sync(0xffffffffu, cB, l);
        float4 va = make_float4(0.f, 0.f, 0.f, 0.f);
        float4 vb = make_float4(0.f, 0.f, 0.f, 0.f);
        if (ia >= 0) va = __ldg((const float4*)x + (size_t)ia * 16 + q);
        if (ib >= 0) vb = __ldg((const float4*)x + (size_t)ib * 16 + q);
        float4 mn = make_float4(fminf(va.x, vb.x), fminf(va.y, vb.y),
                                fminf(va.z, vb.z), fminf(va.w, vb.w));
        MX[i]     = make_float4(fmaxf(va.x, vb.x), fmaxf(va.y, vb.y),
                                fmaxf(va.z, vb.z), fmaxf(va.w, vb.w));
        sts64(bufMin + arow_off(we0 + l, q), f2h2(mn.x, mn.y), f2h2(mn.z, mn.w));
    }
}

__device__ __forceinline__ void sts_max(uint32_t buf, int we0, int q, int half,
                                        const float4* MX) {
#pragma unroll
    for (int i = 0; i < 8; i++) {
        int l = 2 * i + half;
        sts64(buf + arow_off(we0 + l, q),
              f2h2(MX[i].x, MX[i].y), f2h2(MX[i].z, MX[i].w));
    }
}

// ---------------- consumer: one K=64 chunk, warp tile m32 x n32 ----------------
__device__ __forceinline__ void mma_chunk_h(uint32_t aB, const uint4* wrc, int wm,
                                            int lid, float acc[2][4][4]) {
    uint4 Bq[4][2];
#pragma unroll
    for (int nf = 0; nf < 4; nf++)
#pragma unroll
        for (int tp = 0; tp < 2; tp++)
            Bq[nf][tp] = __ldg(wrc + (nf * 2 + tp) * 32);

    const int arow = lid & 15;    // fragment row within m16 block
    const int ksel = lid >> 4;    // which k8 block within the k16 step
#pragma unroll
    for (int t = 0; t < 4; t++) {
        const int kb = 2 * t + ksel;
        uint32_t Af[2][4];
#pragma unroll
        for (int mb = 0; mb < 2; mb++) {
            int row = wm * 32 + mb * 16 + arow;
            ldsm_x4(Af[mb],
                    aB + (uint32_t)(row * 128 + ((kb ^ (row & 7)) << 4)));
        }
#pragma unroll
        for (int mb = 0; mb < 2; mb++)
#pragma unroll
            for (int nf = 0; nf < 4; nf++) {
                uint4 B = Bq[nf][t >> 1];
                uint32_t b0 = (t & 1) ? B.z : B.x;
                uint32_t b1 = (t & 1) ? B.w : B.y;
                mma_f16(acc[mb][nf], Af[mb], b0, b1);
            }
    }
}

// ---------------- main kernel ----------------
// K=320 chunks: c0:x c1:min01 c2:max01 c3:min23 c4:max23
// TILE_M=128, 256 thr, 2 CTAs/SM (48KB smem, <=128 regs). Uniform warps:
// producer warp owns 16 edges; consumer m32 x n32 (4m x 2n).
// 3-buffer ring, 5 phases, sync after s0..s3 (s4 writes nothing shared).
__global__ void __launch_bounds__(NTHREADS, 2)
meshconv_kernel(const float* __restrict__ x, const int* __restrict__ nbr,
                const float* __restrict__ bias, float* __restrict__ out) {
    extern __shared__ char smem[];
    const uint32_t sb = smem_u32(smem);
    const int tid = threadIdx.x;
    const int lid = tid & 31, wid = tid >> 5;
    // consumer identity
    const int wm = wid & 3, wn = wid >> 2;
    const int g = lid >> 2, tig = lid & 3;
    // producer identity
    const int q = lid & 15, half = lid >> 4;
    const int we0 = wid * 16;

    // bias fragment (accumulator init values)
    float bv[4][2];
#pragma unroll
    for (int nf = 0; nf < 4; nf++) {
        int bc = wn * 32 + nf * 8 + tig * 2;
        bv[nf][0] = __ldg(bias + bc);
        bv[nf][1] = __ldg(bias + bc + 1);
    }

    const uint4* wrbase = WrepH + wn * 256 + lid;   // + (c*2)*256 per chunk

    // ---- prologue: NB + stage c0 of first tile into buf 0 ----
    int tile = blockIdx.x;
    int base = tile * TILE_M + we0;
    int NBx, NBy, NBz, NBw;
    {
        int e = base + (lid & 15);
        if (e > E_TOTAL - 1) e = E_TOTAL - 1;
        int4 v = __ldg((const int4*)nbr + e);
        NBx = v.x; NBy = v.y; NBz = v.z; NBw = v.w;
    }
    stage_x(x, base, sb, we0, q, half);
    __syncthreads();

    int bc3 = 0;   // buffer rotation: buf(j) = (bc3 + j) % 3
    for (; tile < NTILES; tile += gridDim.x) {
        int tn = tile + gridDim.x;
        if (tn >= NTILES) tn = tile;
        const int nbase = tn * TILE_M + we0;
        const int tbase = tile * TILE_M;

        const int u1 = (bc3 + 1 == 3) ? 0 : bc3 + 1;
        const int u2 = (u1 + 1 == 3) ? 0 : u1 + 1;
        const uint32_t b_c0 = sb + (uint32_t)bc3 * 16384u;   // c0, c3
        const uint32_t b_c1 = sb + (uint32_t)u1 * 16384u;    // c1, c4
        const uint32_t b_c2 = sb + (uint32_t)u2 * 16384u;    // c2, next c0

        float acc[2][4][4];
#pragma unroll
        for (int mb = 0; mb < 2; mb++)
#pragma unroll
            for (int nf = 0; nf < 4; nf++) {
                acc[mb][nf][0] = bv[nf][0];
                acc[mb][nf][1] = bv[nf][1];
                acc[mb][nf][2] = bv[nf][0];
                acc[mb][nf][3] = bv[nf][1];
            }

        float4 MX[8];   // held max stream (one pair at a time; 32 regs)

        // s0: pair0 -> min01 into b_c1 (hold max01); mma c0(b_c0)
        pair_do(x, NBx, NBy, q, half, we0, b_c1, MX);
        mma_chunk_h(b_c0, wrbase + 0 * 512, wm, lid, acc);
        __syncthreads();

        // s1: STS max01 -> b_c2; pair1 -> min23 into b_c0 (hold max23); mma c1(b_c1)
        sts_max(b_c2, we0, q, half, MX);
        pair_do(x, NBz, NBw, q, half, we0, b_c0, MX);
        mma_chunk_h(b_c1, wrbase + 1 * 512, wm, lid, acc);
        __syncthreads();

        // s2: STS max23 -> b_c1; prefetch next NB; mma c2(b_c2)
        sts_max(b_c1, we0, q, half, MX);
        int NBnx, NBny, NBnz, NBnw;
        {
            int e = nbase + (lid & 15);
            if (e > E_TOTAL - 1) e = E_TOTAL - 1;
            int4 v = __ldg((const int4*)nbr + e);
            NBnx = v.x; NBny = v.y; NBnz = v.z; NBnw = v.w;
        }
        mma_chunk_h(b_c2, wrbase + 2 * 512, wm, lid, acc);
        __syncthreads();

        // s3: stage next tile's c0 (x) -> b_c2; mma c3(b_c0)
        stage_x(x, nbase, b_c2, we0, q, half);
        mma_chunk_h(b_c0, wrbase + 3 * 512, wm, lid, acc);
        __syncthreads();

        // s4: mma c4(b_c1); rotate; epilogue (pure STG, no smem writes -> no sync)
        mma_chunk_h(b_c1, wrbase + 4 * 512, wm, lid, acc);
        NBx = NBnx; NBy = NBny; NBz = NBnz; NBw = NBnw;
        base = nbase;
        bc3 = u2;

#pragma unroll
        for (int mb = 0; mb < 2; mb++) {
#pragma unroll
            for (int nf = 0; nf < 4; nf++) {
                const int e0  = tbase + wm * 32 + mb * 16 + g;
                const int e1  = e0 + 8;
                const int col = wn * 32 + nf * 8 + tig * 2;
                if (e0 < E_TOTAL)
                    *(float2*)(out + (size_t)e0 * 64 + col) =
                        make_float2(acc[mb][nf][0], acc[mb][nf][1]);
                if (e1 < E_TOTAL)
                    *(float2*)(out + (size_t)e1 * 64 + col) =
                        make_float2(acc[mb][nf][2], acc[mb][nf][3]);
            }
        }
    }
}

// ---------------- launch ----------------
extern "C" void kernel_launch(void* const* d_in, const int* in_sizes, int n_in,
                              void* d_out, int out_size) {
    const float* x   = (const float*)d_in[0];
    const int*   nbr = (const int*)d_in[1];
    const float* W   = (const float*)d_in[2];
    const float* b   = (const float*)d_in[3];
    float* out = (float*)d_out;

    int nsm = 0;
    cudaDeviceGetAttribute(&nsm, cudaDevAttrMultiProcessorCount, 0);
    if (nsm <= 0) nsm = 148;

    repack_w_h<<<10, 256>>>(W);

    cudaFuncSetAttribute(meshconv_kernel,
                         cudaFuncAttributeMaxDynamicSharedMemorySize, SMEM_TOTAL);
    meshconv_kernel<<<2 * nsm, NTHREADS, SMEM_TOTAL>>>(x, nbr, b, out);
}